// round 6
// baseline (speedup 1.0000x reference)
#include <cuda_runtime.h>

// SpatialTransformer: out = trilinear_sample(src, identity_grid + flow), border clamp.
// src:  [1,1,160,192,160] f32   d_in[0]
// flow: [1,3,160,192,160] f32   d_in[1]  (channel-planar: d,h,w displacement)
// grid: identity meshgrid       d_in[2]  (IGNORED - recomputed from indices)
// out:  [1,1,160,192,160] f32
//
// Math collapse (verified, rel_err 2.6e-5):
//   ux = (w + flow[2]) * W/(W-1) - 0.5 ; clamp [0, W-1]; trilinear w/ clamped +1.
//
// R5 insight: flow is i.i.d. -> each gather LDG touches ~1 distinct L1 line per
// lane; wavefronts/voxel ~= #loads/voxel. So fetch each x-adjacent corner PAIR
// with one 16B-aligned float4 (row offsets zy are multiples of 4 since W=160):
// both x0 and x1=x0+1 are inside the float4 unless x0&3==3 (25%, predicated
// scalar fix-up). 8 loads/voxel -> ~5 -> ~1.6x fewer L1 wavefronts.

#define DD 160
#define HH 192
#define WW 160
#define PLANE (HH * WW)
#define NN (DD * HH * WW)
#define ZB 4   // z-batch per thread

__global__ __launch_bounds__(256) void st_warp_v4_kernel(
    const float* __restrict__ src,
    const float* __restrict__ flow,
    float* __restrict__ out)
{
    const int tid = blockIdx.x * blockDim.x + threadIdx.x;
    if (tid >= NN / ZB) return;

    const int w  = tid % WW;
    const int t  = tid / WW;
    const int h  = t % HH;
    const int dg = t / HH;          // z-group, d = dg*ZB + k
    const int base = (dg * ZB * HH + h) * WW + w;

    const float sx = (float)WW / (float)(WW - 1);
    const float sy = (float)HH / (float)(HH - 1);
    const float sz = (float)DD / (float)(DD - 1);

    float fdv[ZB], fhv[ZB], fwv[ZB];
#pragma unroll
    for (int k = 0; k < ZB; k++) {
        const int idx = base + k * PLANE;
        fdv[k] = __ldg(flow + idx);            // D-displacement
        fhv[k] = __ldg(flow + NN + idx);       // H-displacement
        fwv[k] = __ldg(flow + 2 * NN + idx);   // W-displacement
    }

    float res[ZB];
#pragma unroll
    for (int k = 0; k < ZB; k++) {
        const int d = dg * ZB + k;

        float ux = ((float)w + fwv[k]) * sx - 0.5f;
        float uy = ((float)h + fhv[k]) * sy - 0.5f;
        float uz = ((float)d + fdv[k]) * sz - 0.5f;

        ux = fminf(fmaxf(ux, 0.0f), (float)(WW - 1));
        uy = fminf(fmaxf(uy, 0.0f), (float)(HH - 1));
        uz = fminf(fmaxf(uz, 0.0f), (float)(DD - 1));

        // coords >= 0 -> truncation == floor
        const int x0 = (int)ux;
        const int y0 = (int)uy;
        const int z0 = (int)uz;
        const float ax = ux - (float)x0;
        const float ay = uy - (float)y0;
        const float az = uz - (float)z0;

        const int x1 = min(x0 + 1, WW - 1);
        const int y1 = min(y0 + 1, HH - 1);
        const int z1 = min(z0 + 1, DD - 1);

        const int x0a = x0 & ~3;        // 16B-aligned start (zy offsets are %4==0)
        const int o   = x0 & 3;

        const int zy00 = (z0 * HH + y0) * WW;
        const int zy01 = (z0 * HH + y1) * WW;
        const int zy10 = (z1 * HH + y0) * WW;
        const int zy11 = (z1 * HH + y1) * WW;

        const float4 v00 = __ldg((const float4*)(src + zy00 + x0a));
        const float4 v01 = __ldg((const float4*)(src + zy01 + x0a));
        const float4 v10 = __ldg((const float4*)(src + zy10 + x0a));
        const float4 v11 = __ldg((const float4*)(src + zy11 + x0a));

        // fix-up loads only for lanes with o==3 (pair straddles float4 boundary)
        float e00, e01, e10, e11;
        if (o == 3) {
            e00 = __ldg(src + zy00 + x1);
            e01 = __ldg(src + zy01 + x1);
            e10 = __ldg(src + zy10 + x1);
            e11 = __ldg(src + zy11 + x1);
        } else {
            e00 = e01 = e10 = e11 = 0.0f;  // unused
        }

        // select (lo, hi) from the vector by o, x-lerp per row
        #define ROW_LERP(v, e, dst)                                              \
        {                                                                        \
            float lo = (o == 0) ? v.x : (o == 1) ? v.y : (o == 2) ? v.z : v.w;   \
            float hi = (o == 0) ? v.y : (o == 1) ? v.z : (o == 2) ? v.w : e;     \
            dst = fmaf(ax, hi - lo, lo);                                         \
        }

        float c00, c01, c10, c11;
        ROW_LERP(v00, e00, c00)
        ROW_LERP(v01, e01, c01)
        ROW_LERP(v10, e10, c10)
        ROW_LERP(v11, e11, c11)
        #undef ROW_LERP

        const float c0 = fmaf(ay, c01 - c00, c00);
        const float c1 = fmaf(ay, c11 - c10, c10);
        res[k] = fmaf(az, c1 - c0, c0);
    }

#pragma unroll
    for (int k = 0; k < ZB; k++)
        out[base + k * PLANE] = res[k];
}

extern "C" void kernel_launch(void* const* d_in, const int* in_sizes, int n_in,
                              void* d_out, int out_size)
{
    const float* src  = (const float*)d_in[0];
    const float* flow = (const float*)d_in[1];
    // d_in[2] (identity grid) intentionally unused — recomputed from indices.
    float* out = (float*)d_out;

    const int threads = 256;
    const int blocks = (NN / ZB + threads - 1) / threads;
    st_warp_v4_kernel<<<blocks, threads>>>(src, flow, out);
}

// round 7
// speedup vs baseline: 1.2242x; 1.2242x over previous
#include <cuda_runtime.h>

// SpatialTransformer: out = trilinear_sample(src, identity_grid + flow), border clamp.
// src:  [1,1,160,192,160] f32   d_in[0]
// flow: [1,3,160,192,160] f32   d_in[1]  (channel-planar: d,h,w displacement)
// grid: identity meshgrid       d_in[2]  (IGNORED - recomputed from indices)
// out:  [1,1,160,192,160] f32
//
// Math collapse (verified, rel_err 2.6e-5):
//   ux = (w + flow[2]) * W/(W-1) - 0.5 ; clamp [0, W-1]; trilinear w/ clamped +1.
//
// R6 lesson: LDG.128 pair-fetch doubled L1 return bytes (16B/lane) and blew
// registers (47, occ 59%) -> regression. This round: LDG.64 (float2) at x0&~1
// covers both x-corners for even x0 (50%) with a predicated scalar fix-up for
// odd x0. Return bytes unchanged vs scalar (32B/voxel), gather wavefronts
// ~6/voxel vs 8, registers stay low.

#define DD 160
#define HH 192
#define WW 160
#define PLANE (HH * WW)
#define NN (DD * HH * WW)
#define ZB 4   // z-batch per thread

__global__ __launch_bounds__(256) void st_warp_f2_kernel(
    const float* __restrict__ src,
    const float* __restrict__ flow,
    float* __restrict__ out)
{
    const int tid = blockIdx.x * blockDim.x + threadIdx.x;
    if (tid >= NN / ZB) return;

    const int w  = tid % WW;
    const int t  = tid / WW;
    const int h  = t % HH;
    const int dg = t / HH;          // z-group, d = dg*ZB + k
    const int base = (dg * ZB * HH + h) * WW + w;

    const float sx = (float)WW / (float)(WW - 1);
    const float sy = (float)HH / (float)(HH - 1);
    const float sz = (float)DD / (float)(DD - 1);

    float fdv[ZB], fhv[ZB], fwv[ZB];
#pragma unroll
    for (int k = 0; k < ZB; k++) {
        const int idx = base + k * PLANE;
        fdv[k] = __ldg(flow + idx);            // D-displacement
        fhv[k] = __ldg(flow + NN + idx);       // H-displacement
        fwv[k] = __ldg(flow + 2 * NN + idx);   // W-displacement
    }

    float res[ZB];
#pragma unroll
    for (int k = 0; k < ZB; k++) {
        const int d = dg * ZB + k;

        float ux = ((float)w + fwv[k]) * sx - 0.5f;
        float uy = ((float)h + fhv[k]) * sy - 0.5f;
        float uz = ((float)d + fdv[k]) * sz - 0.5f;

        ux = fminf(fmaxf(ux, 0.0f), (float)(WW - 1));
        uy = fminf(fmaxf(uy, 0.0f), (float)(HH - 1));
        uz = fminf(fmaxf(uz, 0.0f), (float)(DD - 1));

        // coords >= 0 -> truncation == floor
        const int x0 = (int)ux;
        const int y0 = (int)uy;
        const int z0 = (int)uz;
        const float ax = ux - (float)x0;
        const float ay = uy - (float)y0;
        const float az = uz - (float)z0;

        const int x1 = min(x0 + 1, WW - 1);
        const int y1 = min(y0 + 1, HH - 1);
        const int z1 = min(z0 + 1, DD - 1);

        const int x0a = x0 & ~1;        // 8B-aligned pair start (zy % 2 == 0)
        const bool odd = (x0 & 1) != 0;

        const int zy00 = (z0 * HH + y0) * WW;
        const int zy01 = (z0 * HH + y1) * WW;
        const int zy10 = (z1 * HH + y0) * WW;
        const int zy11 = (z1 * HH + y1) * WW;

        const float2 v00 = __ldg((const float2*)(src + zy00 + x0a));
        const float2 v01 = __ldg((const float2*)(src + zy01 + x0a));
        const float2 v10 = __ldg((const float2*)(src + zy10 + x0a));
        const float2 v11 = __ldg((const float2*)(src + zy11 + x0a));

        // predicated fix-up loads for odd x0 (pair straddles float2 boundary)
        float e00 = v00.y, e01 = v01.y, e10 = v10.y, e11 = v11.y;
        if (odd) e00 = __ldg(src + zy00 + x1);
        if (odd) e01 = __ldg(src + zy01 + x1);
        if (odd) e10 = __ldg(src + zy10 + x1);
        if (odd) e11 = __ldg(src + zy11 + x1);

        const float l00 = odd ? v00.y : v00.x;
        const float l01 = odd ? v01.y : v01.x;
        const float l10 = odd ? v10.y : v10.x;
        const float l11 = odd ? v11.y : v11.x;

        const float c00 = fmaf(ax, e00 - l00, l00);
        const float c01 = fmaf(ax, e01 - l01, l01);
        const float c10 = fmaf(ax, e10 - l10, l10);
        const float c11 = fmaf(ax, e11 - l11, l11);

        const float c0 = fmaf(ay, c01 - c00, c00);
        const float c1 = fmaf(ay, c11 - c10, c10);
        res[k] = fmaf(az, c1 - c0, c0);
    }

#pragma unroll
    for (int k = 0; k < ZB; k++)
        out[base + k * PLANE] = res[k];
}

extern "C" void kernel_launch(void* const* d_in, const int* in_sizes, int n_in,
                              void* d_out, int out_size)
{
    const float* src  = (const float*)d_in[0];
    const float* flow = (const float*)d_in[1];
    // d_in[2] (identity grid) intentionally unused — recomputed from indices.
    float* out = (float*)d_out;

    const int threads = 256;
    const int blocks = (NN / ZB + threads - 1) / threads;
    st_warp_f2_kernel<<<blocks, threads>>>(src, flow, out);
}